// round 2
// baseline (speedup 1.0000x reference)
#include <cuda_runtime.h>
#include <math.h>

#define NN 50000
#define EE 800000
#define BN_EPS 1e-3f

// ---------------- scratch (device globals; no allocation allowed) ----------------
__device__ float g_a0[NN * 256];
__device__ float g_a1[NN * 256];
__device__ float g_a2[NN * 256];
__device__ float g_tmp[NN * 256];
__device__ float g_h[NN * 256];
__device__ float g_h2[NN * 256];
__device__ float g_z[NN * 16];
__device__ int   g_rowptr[NN + 1];
__device__ int   g_cnt[NN];
__device__ int   g_cursor[NN];
__device__ int   g_ecol[EE];
__device__ float g_eval[EE];
__device__ float g_Wc0[4 * 128 * 256];
__device__ float g_Wc1[4 * 256 * 256];
__device__ float g_psum[256 * 256];
__device__ float g_psq[256 * 256];
__device__ float g_scale[256];
__device__ float g_shift[256];

// ---------------- CSR build ----------------
__global__ void k_zero_int(int* __restrict__ p, int n) {
    int i = blockIdx.x * blockDim.x + threadIdx.x;
    if (i < n) p[i] = 0;
}

__global__ void k_hist(const int* __restrict__ rows, int* __restrict__ cnt) {
    int e = blockIdx.x * blockDim.x + threadIdx.x;
    if (e < EE) atomicAdd(&cnt[rows[e]], 1);
}

__global__ void k_scan(const int* __restrict__ cnt, int* __restrict__ rowptr) {
    __shared__ int ss[1024];
    int t = threadIdx.x;
    const int chunk = (NN + 1023) / 1024;
    int b = t * chunk;
    int e = min(b + chunk, NN);
    int s = 0;
    for (int i = b; i < e; i++) s += cnt[i];
    ss[t] = s;
    __syncthreads();
    for (int off = 1; off < 1024; off <<= 1) {
        int v = (t >= off) ? ss[t - off] : 0;
        __syncthreads();
        ss[t] += v;
        __syncthreads();
    }
    int run = (t == 0) ? 0 : ss[t - 1];
    for (int i = b; i < e; i++) { rowptr[i] = run; run += cnt[i]; }
    if (t == 1023) rowptr[NN] = ss[1023];
}

__global__ void k_copy_int(const int* __restrict__ a, int* __restrict__ b, int n) {
    int i = blockIdx.x * blockDim.x + threadIdx.x;
    if (i < n) b[i] = a[i];
}

__global__ void k_scatter(const int* __restrict__ rows, const int* __restrict__ cols,
                          const float* __restrict__ vals, int* __restrict__ cursor,
                          int* __restrict__ ecol, float* __restrict__ eval) {
    int e = blockIdx.x * blockDim.x + threadIdx.x;
    if (e < EE) {
        int p = atomicAdd(&cursor[rows[e]], 1);
        ecol[p] = cols[e];
        eval[p] = vals[e];
    }
}

// ---------------- weight prep: Wc[s][k][j2], j2<128 from Walpha, else Wbeta ------
__global__ void k_prep_w(const float* __restrict__ Wa, const float* __restrict__ Wb,
                         float* __restrict__ Wc, int D) {
    int idx = blockIdx.x * blockDim.x + threadIdx.x;
    int tot = 4 * D * 256;
    if (idx >= tot) return;
    int s = idx / (D * 256);
    int rem = idx - s * D * 256;
    int k = rem >> 8;
    int j2 = rem & 255;
    const float* W = (j2 < 128) ? Wa : Wb;
    int j = j2 & 127;
    int sz = D * 128;
    float v;
    if (s == 0) v = W[k * 128 + j] + W[sz + k * 128 + j] + W[2 * sz + k * 128 + j];
    else        v = W[(s + 2) * sz + k * 128 + j];
    Wc[idx] = v;
}

// ---------------- SPMM: y[r,:] = sum_j eval[j] * x[ecol[j],:] (CSR) ----------------
__global__ void k_spmm(const float* __restrict__ x, float* __restrict__ y,
                       const int* __restrict__ rowptr, const int* __restrict__ ecol,
                       const float* __restrict__ eval, int D) {
    int r = blockIdx.x;
    int f = threadIdx.x;
    int s = __ldg(&rowptr[r]);
    int e = __ldg(&rowptr[r + 1]);
    float acc = 0.f;
    int j = s;
    for (; j + 2 <= e; j += 2) {
        int c0 = __ldg(&ecol[j]);
        int c1 = __ldg(&ecol[j + 1]);
        float v0 = __ldg(&eval[j]);
        float v1 = __ldg(&eval[j + 1]);
        acc += v0 * __ldg(&x[(size_t)c0 * D + f]);
        acc += v1 * __ldg(&x[(size_t)c1 * D + f]);
    }
    if (j < e) acc += __ldg(&eval[j]) * __ldg(&x[(size_t)__ldg(&ecol[j]) * D + f]);
    y[(size_t)r * D + f] = acc;
}

// ---------------- GEMM: C(N,256) = sum_s Xs(N,D) @ W[s](D,256); relu on cols<128 ---
__global__ __launch_bounds__(256, 2)
void k_gemm4(const float* __restrict__ X0, const float* __restrict__ X1,
             const float* __restrict__ X2, const float* __restrict__ X3,
             const float* __restrict__ W, float* __restrict__ C,
             int Nrows, int D) {
    __shared__ float As[16][132];
    __shared__ float Bs[16][128];
    const int tid = threadIdx.x;
    const int tx = tid & 15;
    const int ty = tid >> 4;
    const int blockRow = blockIdx.x * 128;
    const int blockCol = blockIdx.y * 128;

    float acc[8][8];
#pragma unroll
    for (int i = 0; i < 8; i++)
#pragma unroll
        for (int j = 0; j < 8; j++) acc[i][j] = 0.f;

    const float* Xs[4] = {X0, X1, X2, X3};

    for (int s = 0; s < 4; ++s) {
        const float* Xp = Xs[s];
        const float* Wp = W + (size_t)s * D * 256;
        for (int kt = 0; kt < D; kt += 16) {
            // load A tile (128x16) transposed into As[k][m]
#pragma unroll
            for (int i = 0; i < 2; ++i) {
                int l = tid + i * 256;
                int aRow = l >> 2;
                int aK = (l & 3) << 2;
                int gr = blockRow + aRow;
                float4 v = make_float4(0.f, 0.f, 0.f, 0.f);
                if (gr < Nrows) v = *(const float4*)&Xp[(size_t)gr * D + kt + aK];
                As[aK + 0][aRow] = v.x;
                As[aK + 1][aRow] = v.y;
                As[aK + 2][aRow] = v.z;
                As[aK + 3][aRow] = v.w;
            }
            // load B tile (16x128)
#pragma unroll
            for (int i = 0; i < 2; ++i) {
                int l = tid + i * 256;
                int bK = l >> 5;
                int bCol = (l & 31) << 2;
                *(float4*)&Bs[bK][bCol] =
                    *(const float4*)&Wp[(size_t)(kt + bK) * 256 + blockCol + bCol];
            }
            __syncthreads();
#pragma unroll
            for (int k = 0; k < 16; ++k) {
                float ar[8], br[8];
                *(float4*)&ar[0] = *(float4*)&As[k][ty * 8];
                *(float4*)&ar[4] = *(float4*)&As[k][ty * 8 + 4];
                *(float4*)&br[0] = *(float4*)&Bs[k][tx * 8];
                *(float4*)&br[4] = *(float4*)&Bs[k][tx * 8 + 4];
#pragma unroll
                for (int i = 0; i < 8; i++)
#pragma unroll
                    for (int j = 0; j < 8; j++) acc[i][j] += ar[i] * br[j];
            }
            __syncthreads();
        }
    }

#pragma unroll
    for (int i = 0; i < 8; i++) {
        int gr = blockRow + ty * 8 + i;
        if (gr >= Nrows) continue;
#pragma unroll
        for (int j = 0; j < 8; j += 4) {
            int gc = blockCol + tx * 8 + j;
            float4 v = make_float4(acc[i][j], acc[i][j + 1], acc[i][j + 2], acc[i][j + 3]);
            if (gc < 128) {  // alpha half: relu before BN
                v.x = fmaxf(v.x, 0.f);
                v.y = fmaxf(v.y, 0.f);
                v.z = fmaxf(v.z, 0.f);
                v.w = fmaxf(v.w, 0.f);
            }
            *(float4*)&C[(size_t)gr * 256 + gc] = v;
        }
    }
}

// ---------------- BatchNorm (training-mode, biased var) ----------------
__global__ void k_bn_stats(const float* __restrict__ h, float* __restrict__ psum,
                           float* __restrict__ psq, int Nrows) {
    int f = threadIdx.x;  // 256 features
    float s = 0.f, q = 0.f;
    for (int r = blockIdx.x; r < Nrows; r += gridDim.x) {
        float v = h[(size_t)r * 256 + f];
        s += v;
        q += v * v;
    }
    psum[blockIdx.x * 256 + f] = s;
    psq[blockIdx.x * 256 + f] = q;
}

__global__ void k_bn_reduce(const float* __restrict__ psum, const float* __restrict__ psq,
                            const float* __restrict__ bnp, float* __restrict__ scale,
                            float* __restrict__ shift) {
    int f = threadIdx.x;  // 256
    double s = 0.0, q = 0.0;
    for (int b = 0; b < 256; b++) {
        s += (double)psum[b * 256 + f];
        q += (double)psq[b * 256 + f];
    }
    double mu = s / (double)NN;
    double var = q / (double)NN - mu * mu;
    float g, bt;
    if (f < 128) { g = bnp[f];            bt = bnp[128 + f]; }
    else         { g = bnp[256 + f - 128]; bt = bnp[384 + f - 128]; }
    float sc = g * rsqrtf((float)var + BN_EPS);
    scale[f] = sc;
    shift[f] = bt - (float)mu * sc;
}

__global__ void k_bn_apply(float* __restrict__ h, const float* __restrict__ scale,
                           const float* __restrict__ shift) {
    int i = blockIdx.x * blockDim.x + threadIdx.x;
    if (i < NN * 256) {
        int c = i & 255;
        h[i] = h[i] * scale[c] + shift[c];
    }
}

// ---------------- z = h2 @ We + be  (N,256)@(256,16) ----------------
__global__ void k_zproj(const float* __restrict__ h, const float* __restrict__ We,
                        const float* __restrict__ be, float* __restrict__ z) {
    __shared__ float Ws[256 * 16];
    for (int i = threadIdx.x; i < 4096; i += blockDim.x) Ws[i] = We[i];
    __syncthreads();
    int t = blockIdx.x * blockDim.x + threadIdx.x;  // exactly NN*16 threads
    int r = t >> 4, m = t & 15;
    float acc = __ldg(&be[m]);
    const float4* hp = (const float4*)(h + (size_t)r * 256);
#pragma unroll 4
    for (int k4 = 0; k4 < 64; k4++) {
        float4 hv = hp[k4];
        int k = k4 * 4;
        acc += hv.x * Ws[k * 16 + m] + hv.y * Ws[(k + 1) * 16 + m] +
               hv.z * Ws[(k + 2) * 16 + m] + hv.w * Ws[(k + 3) * 16 + m];
    }
    z[t] = acc;
}

// ---------------- per-edge score + softmax over 16 machines ----------------
__global__ void k_edge(const int* __restrict__ rows, const int* __restrict__ cols,
                       const float* __restrict__ vals, const float* __restrict__ z,
                       float* __restrict__ out) {
    int idx = blockIdx.x * blockDim.x + threadIdx.x;  // exactly EE*16 threads
    int e = idx >> 4, m = idx & 15;
    int r = __ldg(&rows[e]);
    int c = __ldg(&cols[e]);
    float s = __ldg(&vals[e]) * (__ldg(&z[r * 16 + m]) + __ldg(&z[c * 16 + m]));
    float mx = s;
#pragma unroll
    for (int off = 8; off > 0; off >>= 1)
        mx = fmaxf(mx, __shfl_xor_sync(0xffffffffu, mx, off, 16));
    float ex = __expf(s - mx);
    float sm = ex;
#pragma unroll
    for (int off = 8; off > 0; off >>= 1)
        sm += __shfl_xor_sync(0xffffffffu, sm, off, 16);
    out[idx] = ex / sm;
}

// ---------------- launch ----------------
extern "C" void kernel_launch(void* const* d_in, const int* in_sizes, int n_in,
                              void* d_out, int out_size) {
    const float* x    = (const float*)d_in[0];
    const int*   rows = (const int*)d_in[1];
    const int*   cols = (const int*)d_in[2];
    const float* vals = (const float*)d_in[3];
    const float* l0Wa = (const float*)d_in[4];
    const float* l0Wb = (const float*)d_in[5];
    const float* l0bn = (const float*)d_in[6];
    const float* l1Wa = (const float*)d_in[7];
    const float* l1Wb = (const float*)d_in[8];
    const float* l1bn = (const float*)d_in[9];
    const float* We   = (const float*)d_in[10];
    const float* be   = (const float*)d_in[11];
    float* out = (float*)d_out;

    float *a0, *a1, *a2, *tmp, *h, *h2, *z, *evalp, *wc0, *wc1, *psum, *psq, *scale, *shift;
    int *rowptr, *cnt, *cursor, *ecol;
    cudaGetSymbolAddress((void**)&a0, g_a0);
    cudaGetSymbolAddress((void**)&a1, g_a1);
    cudaGetSymbolAddress((void**)&a2, g_a2);
    cudaGetSymbolAddress((void**)&tmp, g_tmp);
    cudaGetSymbolAddress((void**)&h, g_h);
    cudaGetSymbolAddress((void**)&h2, g_h2);
    cudaGetSymbolAddress((void**)&z, g_z);
    cudaGetSymbolAddress((void**)&evalp, g_eval);
    cudaGetSymbolAddress((void**)&wc0, g_Wc0);
    cudaGetSymbolAddress((void**)&wc1, g_Wc1);
    cudaGetSymbolAddress((void**)&psum, g_psum);
    cudaGetSymbolAddress((void**)&psq, g_psq);
    cudaGetSymbolAddress((void**)&scale, g_scale);
    cudaGetSymbolAddress((void**)&shift, g_shift);
    cudaGetSymbolAddress((void**)&rowptr, g_rowptr);
    cudaGetSymbolAddress((void**)&cnt, g_cnt);
    cudaGetSymbolAddress((void**)&cursor, g_cursor);
    cudaGetSymbolAddress((void**)&ecol, g_ecol);

    // ---- CSR build (in-graph, deterministic counts) ----
    k_zero_int<<<(NN + 255) / 256, 256>>>(cnt, NN);
    k_hist<<<(EE + 255) / 256, 256>>>(rows, cnt);
    k_scan<<<1, 1024>>>(cnt, rowptr);
    k_copy_int<<<(NN + 255) / 256, 256>>>(rowptr, cursor, NN);
    k_scatter<<<(EE + 255) / 256, 256>>>(rows, cols, vals, cursor, ecol, evalp);

    // ---- combined weights ----
    k_prep_w<<<(4 * 128 * 256 + 255) / 256, 256>>>(l0Wa, l0Wb, wc0, 128);
    k_prep_w<<<(4 * 256 * 256 + 255) / 256, 256>>>(l1Wa, l1Wb, wc1, 256);

    dim3 ggrid((NN + 127) / 128, 2);

    // ---- layer 0 (D = 128) ----
    k_spmm<<<NN, 128>>>(x, a0, rowptr, ecol, evalp, 128);
    k_spmm<<<NN, 128>>>(a0, a1, rowptr, ecol, evalp, 128);
    k_spmm<<<NN, 128>>>(a1, tmp, rowptr, ecol, evalp, 128);
    k_spmm<<<NN, 128>>>(tmp, a2, rowptr, ecol, evalp, 128);
    k_gemm4<<<ggrid, 256>>>(x, a0, a1, a2, wc0, h, NN, 128);
    k_bn_stats<<<256, 256>>>(h, psum, psq, NN);
    k_bn_reduce<<<1, 256>>>(psum, psq, l0bn, scale, shift);
    k_bn_apply<<<(NN * 256 + 255) / 256, 256>>>(h, scale, shift);

    // ---- layer 1 (D = 256) ----
    k_spmm<<<NN, 256>>>(h, a0, rowptr, ecol, evalp, 256);
    k_spmm<<<NN, 256>>>(a0, a1, rowptr, ecol, evalp, 256);
    k_spmm<<<NN, 256>>>(a1, tmp, rowptr, ecol, evalp, 256);
    k_spmm<<<NN, 256>>>(tmp, a2, rowptr, ecol, evalp, 256);
    k_gemm4<<<ggrid, 256>>>(h, a0, a1, a2, wc1, h2, NN, 256);
    k_bn_stats<<<256, 256>>>(h2, psum, psq, NN);
    k_bn_reduce<<<1, 256>>>(psum, psq, l1bn, scale, shift);
    k_bn_apply<<<(NN * 256 + 255) / 256, 256>>>(h2, scale, shift);

    // ---- final projection + per-edge softmax ----
    k_zproj<<<(NN * 16) / 256, 256>>>(h2, We, be, z);
    k_edge<<<(EE * 16) / 256, 256>>>(rows, cols, vals, z, out);
}

// round 3
// speedup vs baseline: 1.2656x; 1.2656x over previous
#include <cuda_runtime.h>
#include <math.h>

#define NN 50000
#define EE 800000
#define BN_EPS 1e-3f

// ---------------- scratch (device globals; no allocation allowed) ----------------
__device__ float g_a0[NN * 256];
__device__ float g_a1[NN * 256];
__device__ float g_a2[NN * 256];
__device__ float g_tmp[NN * 256];
__device__ float g_h[NN * 256];
__device__ float g_h2[NN * 256];
__device__ float g_z[NN * 16];
__device__ int   g_rowptr[NN + 1];
__device__ int   g_cnt[NN];
__device__ int   g_cursor[NN];
__device__ int   g_ecol[EE];
__device__ float g_eval[EE];
__device__ float g_Wc0[4 * 128 * 256];
__device__ float g_Wc1[4 * 256 * 256];
__device__ float g_psum[256 * 256];
__device__ float g_psq[256 * 256];
__device__ float g_scale[256];
__device__ float g_shift[256];

// ---------------- packed f32x2 helpers ----------------
__device__ __forceinline__ unsigned long long pack2(float lo, float hi) {
    unsigned long long r;
    asm("mov.b64 %0, {%1, %2};" : "=l"(r) : "r"(__float_as_uint(lo)), "r"(__float_as_uint(hi)));
    return r;
}
__device__ __forceinline__ void unpack2(unsigned long long v, float& lo, float& hi) {
    unsigned int a, b;
    asm("mov.b64 {%0, %1}, %2;" : "=r"(a), "=r"(b) : "l"(v));
    lo = __uint_as_float(a);
    hi = __uint_as_float(b);
}
__device__ __forceinline__ void ffma2(unsigned long long& d, unsigned long long a,
                                      unsigned long long b) {
    asm("fma.rn.f32x2 %0, %1, %2, %0;" : "+l"(d) : "l"(a), "l"(b));
}

// ---------------- CSR build ----------------
__global__ void k_zero_int(int* __restrict__ p, int n) {
    int i = blockIdx.x * blockDim.x + threadIdx.x;
    if (i < n) p[i] = 0;
}

__global__ void k_hist(const int* __restrict__ rows, int* __restrict__ cnt) {
    int e = blockIdx.x * blockDim.x + threadIdx.x;
    if (e < EE) atomicAdd(&cnt[rows[e]], 1);
}

__global__ void k_scan(const int* __restrict__ cnt, int* __restrict__ rowptr) {
    __shared__ int ss[1024];
    int t = threadIdx.x;
    const int chunk = (NN + 1023) / 1024;
    int b = t * chunk;
    int e = min(b + chunk, NN);
    int s = 0;
    for (int i = b; i < e; i++) s += cnt[i];
    ss[t] = s;
    __syncthreads();
    for (int off = 1; off < 1024; off <<= 1) {
        int v = (t >= off) ? ss[t - off] : 0;
        __syncthreads();
        ss[t] += v;
        __syncthreads();
    }
    int run = (t == 0) ? 0 : ss[t - 1];
    for (int i = b; i < e; i++) { rowptr[i] = run; run += cnt[i]; }
    if (t == 1023) rowptr[NN] = ss[1023];
}

__global__ void k_copy_int(const int* __restrict__ a, int* __restrict__ b, int n) {
    int i = blockIdx.x * blockDim.x + threadIdx.x;
    if (i < n) b[i] = a[i];
}

__global__ void k_scatter(const int* __restrict__ rows, const int* __restrict__ cols,
                          const float* __restrict__ vals, int* __restrict__ cursor,
                          int* __restrict__ ecol, float* __restrict__ eval) {
    int e = blockIdx.x * blockDim.x + threadIdx.x;
    if (e < EE) {
        int p = atomicAdd(&cursor[rows[e]], 1);
        ecol[p] = cols[e];
        eval[p] = vals[e];
    }
}

// ---------------- weight prep: Wc[s][k][j2], j2<128 from Walpha, else Wbeta ------
__global__ void k_prep_w(const float* __restrict__ Wa, const float* __restrict__ Wb,
                         float* __restrict__ Wc, int D) {
    int idx = blockIdx.x * blockDim.x + threadIdx.x;
    int tot = 4 * D * 256;
    if (idx >= tot) return;
    int s = idx / (D * 256);
    int rem = idx - s * D * 256;
    int k = rem >> 8;
    int j2 = rem & 255;
    const float* W = (j2 < 128) ? Wa : Wb;
    int j = j2 & 127;
    int sz = D * 128;
    float v;
    if (s == 0) v = W[k * 128 + j] + W[sz + k * 128 + j] + W[2 * sz + k * 128 + j];
    else        v = W[(s + 2) * sz + k * 128 + j];
    Wc[idx] = v;
}

// ---------------- SPMM (vectorized): y[r,:] = sum_j eval[j] * x[ecol[j],:] -------
template <int DQ, int RPB>
__global__ void k_spmm_v(const float4* __restrict__ x, float4* __restrict__ y,
                         const int* __restrict__ rowptr, const int* __restrict__ ecol,
                         const float* __restrict__ eval) {
    int rl = threadIdx.x / DQ;
    int f = threadIdx.x % DQ;
    int r = blockIdx.x * RPB + rl;
    if (r >= NN) return;
    int s = __ldg(&rowptr[r]);
    int e = __ldg(&rowptr[r + 1]);
    float4 acc = make_float4(0.f, 0.f, 0.f, 0.f);
    int j = s;
    for (; j + 4 <= e; j += 4) {
        int c0 = __ldg(&ecol[j]);
        int c1 = __ldg(&ecol[j + 1]);
        int c2 = __ldg(&ecol[j + 2]);
        int c3 = __ldg(&ecol[j + 3]);
        float v0 = __ldg(&eval[j]);
        float v1 = __ldg(&eval[j + 1]);
        float v2 = __ldg(&eval[j + 2]);
        float v3 = __ldg(&eval[j + 3]);
        float4 x0 = __ldg(&x[(size_t)c0 * DQ + f]);
        float4 x1 = __ldg(&x[(size_t)c1 * DQ + f]);
        float4 x2 = __ldg(&x[(size_t)c2 * DQ + f]);
        float4 x3 = __ldg(&x[(size_t)c3 * DQ + f]);
        acc.x = fmaf(v0, x0.x, acc.x); acc.y = fmaf(v0, x0.y, acc.y);
        acc.z = fmaf(v0, x0.z, acc.z); acc.w = fmaf(v0, x0.w, acc.w);
        acc.x = fmaf(v1, x1.x, acc.x); acc.y = fmaf(v1, x1.y, acc.y);
        acc.z = fmaf(v1, x1.z, acc.z); acc.w = fmaf(v1, x1.w, acc.w);
        acc.x = fmaf(v2, x2.x, acc.x); acc.y = fmaf(v2, x2.y, acc.y);
        acc.z = fmaf(v2, x2.z, acc.z); acc.w = fmaf(v2, x2.w, acc.w);
        acc.x = fmaf(v3, x3.x, acc.x); acc.y = fmaf(v3, x3.y, acc.y);
        acc.z = fmaf(v3, x3.z, acc.z); acc.w = fmaf(v3, x3.w, acc.w);
    }
    for (; j < e; j++) {
        int c = __ldg(&ecol[j]);
        float v = __ldg(&eval[j]);
        float4 xv = __ldg(&x[(size_t)c * DQ + f]);
        acc.x = fmaf(v, xv.x, acc.x); acc.y = fmaf(v, xv.y, acc.y);
        acc.z = fmaf(v, xv.z, acc.z); acc.w = fmaf(v, xv.w, acc.w);
    }
    y[(size_t)r * DQ + f] = acc;
}

// ---------------- GEMM: C(N,256) = sum_s Xs(N,D) @ W[s](D,256); relu per-block ---
__global__ __launch_bounds__(256, 2)
void k_gemm4(const float* __restrict__ X0, const float* __restrict__ X1,
             const float* __restrict__ X2, const float* __restrict__ X3,
             const float* __restrict__ W, float* __restrict__ C,
             int Nrows, int D) {
    __shared__ float As[16][132];
    __shared__ float Bs[16][128];
    const int tid = threadIdx.x;
    const int tx = tid & 15;
    const int ty = tid >> 4;
    const int blockRow = blockIdx.x * 128;
    const int blockCol = blockIdx.y * 128;
    const bool doRelu = (blockIdx.y == 0);  // cols 0..127 = alpha (relu before BN)

    unsigned long long acc2[8][4];
#pragma unroll
    for (int i = 0; i < 8; i++)
#pragma unroll
        for (int j = 0; j < 4; j++) acc2[i][j] = pack2(0.f, 0.f);

    for (int s = 0; s < 4; ++s) {
        const float* Xp = (s == 0) ? X0 : (s == 1) ? X1 : (s == 2) ? X2 : X3;
        const float* Wp = W + (size_t)s * D * 256;
        for (int kt = 0; kt < D; kt += 16) {
            // load A tile (128x16) transposed into As[k][m]
#pragma unroll
            for (int i = 0; i < 2; ++i) {
                int l = tid + i * 256;
                int aRow = l >> 2;
                int aK = (l & 3) << 2;
                int gr = blockRow + aRow;
                float4 v = make_float4(0.f, 0.f, 0.f, 0.f);
                if (gr < Nrows) v = *(const float4*)&Xp[(size_t)gr * D + kt + aK];
                As[aK + 0][aRow] = v.x;
                As[aK + 1][aRow] = v.y;
                As[aK + 2][aRow] = v.z;
                As[aK + 3][aRow] = v.w;
            }
            // load B tile (16x128)
#pragma unroll
            for (int i = 0; i < 2; ++i) {
                int l = tid + i * 256;
                int bK = l >> 5;
                int bCol = (l & 31) << 2;
                *(float4*)&Bs[bK][bCol] =
                    *(const float4*)&Wp[(size_t)(kt + bK) * 256 + blockCol + bCol];
            }
            __syncthreads();
#pragma unroll
            for (int k = 0; k < 16; ++k) {
                float4 a0v = *(float4*)&As[k][ty * 8];
                float4 a1v = *(float4*)&As[k][ty * 8 + 4];
                float4 b0v = *(float4*)&Bs[k][tx * 8];
                float4 b1v = *(float4*)&Bs[k][tx * 8 + 4];
                unsigned long long b2[4];
                b2[0] = pack2(b0v.x, b0v.y);
                b2[1] = pack2(b0v.z, b0v.w);
                b2[2] = pack2(b1v.x, b1v.y);
                b2[3] = pack2(b1v.z, b1v.w);
                float ar[8] = {a0v.x, a0v.y, a0v.z, a0v.w, a1v.x, a1v.y, a1v.z, a1v.w};
#pragma unroll
                for (int i = 0; i < 8; i++) {
                    unsigned long long ap = pack2(ar[i], ar[i]);
#pragma unroll
                    for (int j = 0; j < 4; j++) ffma2(acc2[i][j], ap, b2[j]);
                }
            }
            __syncthreads();
        }
    }

#pragma unroll
    for (int i = 0; i < 8; i++) {
        int gr = blockRow + ty * 8 + i;
        if (gr >= Nrows) continue;
        float vv[8];
#pragma unroll
        for (int j = 0; j < 4; j++) unpack2(acc2[i][j], vv[2 * j], vv[2 * j + 1]);
        if (doRelu) {
#pragma unroll
            for (int j = 0; j < 8; j++) vv[j] = fmaxf(vv[j], 0.f);
        }
        int gc = blockCol + tx * 8;
        *(float4*)&C[(size_t)gr * 256 + gc] = make_float4(vv[0], vv[1], vv[2], vv[3]);
        *(float4*)&C[(size_t)gr * 256 + gc + 4] = make_float4(vv[4], vv[5], vv[6], vv[7]);
    }
}

// ---------------- BatchNorm (training-mode, biased var) ----------------
__global__ void k_bn_stats(const float* __restrict__ h, float* __restrict__ psum,
                           float* __restrict__ psq, int Nrows) {
    int f = threadIdx.x;  // 256 features
    float s = 0.f, q = 0.f;
    for (int r = blockIdx.x; r < Nrows; r += gridDim.x) {
        float v = h[(size_t)r * 256 + f];
        s += v;
        q += v * v;
    }
    psum[blockIdx.x * 256 + f] = s;
    psq[blockIdx.x * 256 + f] = q;
}

__global__ void k_bn_reduce(const float* __restrict__ psum, const float* __restrict__ psq,
                            const float* __restrict__ bnp, float* __restrict__ scale,
                            float* __restrict__ shift) {
    int f = threadIdx.x;  // 256
    double s = 0.0, q = 0.0;
    for (int b = 0; b < 256; b++) {
        s += (double)psum[b * 256 + f];
        q += (double)psq[b * 256 + f];
    }
    double mu = s / (double)NN;
    double var = q / (double)NN - mu * mu;
    float g, bt;
    if (f < 128) { g = bnp[f];             bt = bnp[128 + f]; }
    else         { g = bnp[256 + f - 128]; bt = bnp[384 + f - 128]; }
    float sc = g * rsqrtf((float)var + BN_EPS);
    scale[f] = sc;
    shift[f] = bt - (float)mu * sc;
}

__global__ void k_bn_apply(float4* __restrict__ h, const float* __restrict__ scale,
                           const float* __restrict__ shift) {
    int i = blockIdx.x * blockDim.x + threadIdx.x;  // NN*64 threads
    if (i >= NN * 64) return;
    int c = (i & 63) * 4;
    float4 v = h[i];
    v.x = fmaf(v.x, scale[c + 0], shift[c + 0]);
    v.y = fmaf(v.y, scale[c + 1], shift[c + 1]);
    v.z = fmaf(v.z, scale[c + 2], shift[c + 2]);
    v.w = fmaf(v.w, scale[c + 3], shift[c + 3]);
    h[i] = v;
}

// ---------------- z = h2 @ We + be  (N,256)@(256,16) ----------------
__global__ void k_zproj(const float* __restrict__ h, const float* __restrict__ We,
                        const float* __restrict__ be, float* __restrict__ z) {
    __shared__ float Ws[256 * 16];
    for (int i = threadIdx.x; i < 4096; i += blockDim.x) Ws[i] = We[i];
    __syncthreads();
    int t = blockIdx.x * blockDim.x + threadIdx.x;  // exactly NN*16 threads
    int r = t >> 4, m = t & 15;
    float acc = __ldg(&be[m]);
    const float4* hp = (const float4*)(h + (size_t)r * 256);
#pragma unroll 4
    for (int k4 = 0; k4 < 64; k4++) {
        float4 hv = hp[k4];
        int k = k4 * 4;
        acc += hv.x * Ws[k * 16 + m] + hv.y * Ws[(k + 1) * 16 + m] +
               hv.z * Ws[(k + 2) * 16 + m] + hv.w * Ws[(k + 3) * 16 + m];
    }
    z[t] = acc;
}

// ---------------- per-edge score + softmax over 16 machines ----------------
__global__ void k_edge(const int* __restrict__ rows, const int* __restrict__ cols,
                       const float* __restrict__ vals, const float* __restrict__ z,
                       float* __restrict__ out) {
    int idx = blockIdx.x * blockDim.x + threadIdx.x;  // exactly EE*16 threads
    int e = idx >> 4, m = idx & 15;
    int r = __ldg(&rows[e]);
    int c = __ldg(&cols[e]);
    float s = __ldg(&vals[e]) * (__ldg(&z[r * 16 + m]) + __ldg(&z[c * 16 + m]));
    float mx = s;
#pragma unroll
    for (int off = 8; off > 0; off >>= 1)
        mx = fmaxf(mx, __shfl_xor_sync(0xffffffffu, mx, off, 16));
    float ex = __expf(s - mx);
    float sm = ex;
#pragma unroll
    for (int off = 8; off > 0; off >>= 1)
        sm += __shfl_xor_sync(0xffffffffu, sm, off, 16);
    out[idx] = ex / sm;
}

// ---------------- launch ----------------
extern "C" void kernel_launch(void* const* d_in, const int* in_sizes, int n_in,
                              void* d_out, int out_size) {
    const float* x    = (const float*)d_in[0];
    const int*   rows = (const int*)d_in[1];
    const int*   cols = (const int*)d_in[2];
    const float* vals = (const float*)d_in[3];
    const float* l0Wa = (const float*)d_in[4];
    const float* l0Wb = (const float*)d_in[5];
    const float* l0bn = (const float*)d_in[6];
    const float* l1Wa = (const float*)d_in[7];
    const float* l1Wb = (const float*)d_in[8];
    const float* l1bn = (const float*)d_in[9];
    const float* We   = (const float*)d_in[10];
    const float* be   = (const float*)d_in[11];
    float* out = (float*)d_out;

    float *a0, *a1, *a2, *tmp, *h, *h2, *z, *evalp, *wc0, *wc1, *psum, *psq, *scale, *shift;
    int *rowptr, *cnt, *cursor, *ecol;
    cudaGetSymbolAddress((void**)&a0, g_a0);
    cudaGetSymbolAddress((void**)&a1, g_a1);
    cudaGetSymbolAddress((void**)&a2, g_a2);
    cudaGetSymbolAddress((void**)&tmp, g_tmp);
    cudaGetSymbolAddress((void**)&h, g_h);
    cudaGetSymbolAddress((void**)&h2, g_h2);
    cudaGetSymbolAddress((void**)&z, g_z);
    cudaGetSymbolAddress((void**)&evalp, g_eval);
    cudaGetSymbolAddress((void**)&wc0, g_Wc0);
    cudaGetSymbolAddress((void**)&wc1, g_Wc1);
    cudaGetSymbolAddress((void**)&psum, g_psum);
    cudaGetSymbolAddress((void**)&psq, g_psq);
    cudaGetSymbolAddress((void**)&scale, g_scale);
    cudaGetSymbolAddress((void**)&shift, g_shift);
    cudaGetSymbolAddress((void**)&rowptr, g_rowptr);
    cudaGetSymbolAddress((void**)&cnt, g_cnt);
    cudaGetSymbolAddress((void**)&cursor, g_cursor);
    cudaGetSymbolAddress((void**)&ecol, g_ecol);

    // ---- CSR build (in-graph, deterministic counts) ----
    k_zero_int<<<(NN + 255) / 256, 256>>>(cnt, NN);
    k_hist<<<(EE + 255) / 256, 256>>>(rows, cnt);
    k_scan<<<1, 1024>>>(cnt, rowptr);
    k_copy_int<<<(NN + 255) / 256, 256>>>(rowptr, cursor, NN);
    k_scatter<<<(EE + 255) / 256, 256>>>(rows, cols, vals, cursor, ecol, evalp);

    // ---- combined weights ----
    k_prep_w<<<(4 * 128 * 256 + 255) / 256, 256>>>(l0Wa, l0Wb, wc0, 128);
    k_prep_w<<<(4 * 256 * 256 + 255) / 256, 256>>>(l1Wa, l1Wb, wc1, 256);

    dim3 ggrid((NN + 127) / 128, 2);

    // ---- layer 0 (D = 128, DQ = 32) ----
    k_spmm_v<32, 4><<<(NN + 3) / 4, 128>>>((const float4*)x, (float4*)a0, rowptr, ecol, evalp);
    k_spmm_v<32, 4><<<(NN + 3) / 4, 128>>>((const float4*)a0, (float4*)a1, rowptr, ecol, evalp);
    k_spmm_v<32, 4><<<(NN + 3) / 4, 128>>>((const float4*)a1, (float4*)tmp, rowptr, ecol, evalp);
    k_spmm_v<32, 4><<<(NN + 3) / 4, 128>>>((const float4*)tmp, (float4*)a2, rowptr, ecol, evalp);
    k_gemm4<<<ggrid, 256>>>(x, a0, a1, a2, wc0, h, NN, 128);
    k_bn_stats<<<256, 256>>>(h, psum, psq, NN);
    k_bn_reduce<<<1, 256>>>(psum, psq, l0bn, scale, shift);
    k_bn_apply<<<(NN * 64 + 255) / 256, 256>>>((float4*)h, scale, shift);

    // ---- layer 1 (D = 256, DQ = 64) ----
    k_spmm_v<64, 2><<<(NN + 1) / 2, 128>>>((const float4*)h, (float4*)a0, rowptr, ecol, evalp);
    k_spmm_v<64, 2><<<(NN + 1) / 2, 128>>>((const float4*)a0, (float4*)a1, rowptr, ecol, evalp);
    k_spmm_v<64, 2><<<(NN + 1) / 2, 128>>>((const float4*)a1, (float4*)tmp, rowptr, ecol, evalp);
    k_spmm_v<64, 2><<<(NN + 1) / 2, 128>>>((const float4*)tmp, (float4*)a2, rowptr, ecol, evalp);
    k_gemm4<<<ggrid, 256>>>(h, a0, a1, a2, wc1, h2, NN, 256);
    k_bn_stats<<<256, 256>>>(h2, psum, psq, NN);
    k_bn_reduce<<<1, 256>>>(psum, psq, l1bn, scale, shift);
    k_bn_apply<<<(NN * 64 + 255) / 256, 256>>>((float4*)h2, scale, shift);

    // ---- final projection + per-edge softmax ----
    k_zproj<<<(NN * 16) / 256, 256>>>(h2, We, be, z);
    k_edge<<<(EE * 16) / 256, 256>>>(rows, cols, vals, z, out);
}

// round 7
// speedup vs baseline: 1.6199x; 1.2800x over previous
#include <cuda_runtime.h>
#include <cuda_bf16.h>
#include <math.h>
#include <stdint.h>

#define NN 50000
#define EE 800000
#define BN_EPS 1e-3f

// ---------------- scratch (device globals; no allocation allowed) ----------------
__device__ float g_a0[NN * 256];
__device__ float g_a1[NN * 256];
__device__ float g_a2[NN * 256];
__device__ float g_tmp[NN * 256];
__device__ float g_h[NN * 256];
__device__ float g_h2[NN * 256];
__device__ float g_z[NN * 16];
__device__ int   g_rowptr[NN + 1];
__device__ int   g_cnt[NN];
__device__ int   g_cursor[NN];
__device__ int   g_ecol[EE];
__device__ float g_eval[EE];
__device__ float g_psum[256 * 256];
__device__ float g_psq[256 * 256];
__device__ float g_scale[256];
__device__ float g_shift[256];
// bf16 hi/lo feature buffers (concatenated hop features)
__device__ __nv_bfloat16 g_X0h[NN * 512];
__device__ __nv_bfloat16 g_X0l[NN * 512];
__device__ __nv_bfloat16 g_X1h[(size_t)NN * 1024];
__device__ __nv_bfloat16 g_X1l[(size_t)NN * 1024];
// transposed combined weights (256, K) bf16 hi/lo
__device__ __nv_bfloat16 g_Bt0h[256 * 512];
__device__ __nv_bfloat16 g_Bt0l[256 * 512];
__device__ __nv_bfloat16 g_Bt1h[256 * 1024];
__device__ __nv_bfloat16 g_Bt1l[256 * 1024];

// ---------------- helpers ----------------
__device__ __forceinline__ uint32_t smem_to_u32(const void* p) {
    uint32_t a;
    asm("{ .reg .u64 t; cvta.to.shared.u64 t, %1; cvt.u32.u64 %0, t; }" : "=r"(a) : "l"(p));
    return a;
}
__device__ __forceinline__ void ldsm4(uint32_t* r, uint32_t addr) {
    asm volatile("ldmatrix.sync.aligned.m8n8.x4.shared.b16 {%0,%1,%2,%3}, [%4];"
                 : "=r"(r[0]), "=r"(r[1]), "=r"(r[2]), "=r"(r[3]) : "r"(addr));
}
__device__ __forceinline__ void mma16816(float* c, const uint32_t* a, const uint32_t* b) {
    asm volatile(
        "mma.sync.aligned.m16n8k16.row.col.f32.bf16.bf16.f32 "
        "{%0,%1,%2,%3}, {%4,%5,%6,%7}, {%8,%9}, {%0,%1,%2,%3};"
        : "+f"(c[0]), "+f"(c[1]), "+f"(c[2]), "+f"(c[3])
        : "r"(a[0]), "r"(a[1]), "r"(a[2]), "r"(a[3]), "r"(b[0]), "r"(b[1]));
}
__device__ __forceinline__ void split_bf16(float v, __nv_bfloat16& hi, __nv_bfloat16& lo) {
    hi = __float2bfloat16(v);
    lo = __float2bfloat16(v - __bfloat162float(hi));
}

// ---------------- CSR build ----------------
__global__ void k_zero_int(int* __restrict__ p, int n) {
    int i = blockIdx.x * blockDim.x + threadIdx.x;
    if (i < n) p[i] = 0;
}
__global__ void k_hist(const int* __restrict__ rows, int* __restrict__ cnt) {
    int e = blockIdx.x * blockDim.x + threadIdx.x;
    if (e < EE) atomicAdd(&cnt[rows[e]], 1);
}
__global__ void k_scan(const int* __restrict__ cnt, int* __restrict__ rowptr) {
    __shared__ int ss[1024];
    int t = threadIdx.x;
    const int chunk = (NN + 1023) / 1024;
    int b = t * chunk;
    int e = min(b + chunk, NN);
    int s = 0;
    for (int i = b; i < e; i++) s += cnt[i];
    ss[t] = s;
    __syncthreads();
    for (int off = 1; off < 1024; off <<= 1) {
        int v = (t >= off) ? ss[t - off] : 0;
        __syncthreads();
        ss[t] += v;
        __syncthreads();
    }
    int run = (t == 0) ? 0 : ss[t - 1];
    for (int i = b; i < e; i++) { rowptr[i] = run; run += cnt[i]; }
    if (t == 1023) rowptr[NN] = ss[1023];
}
__global__ void k_copy_int(const int* __restrict__ a, int* __restrict__ b, int n) {
    int i = blockIdx.x * blockDim.x + threadIdx.x;
    if (i < n) b[i] = a[i];
}
__global__ void k_scatter(const int* __restrict__ rows, const int* __restrict__ cols,
                          const float* __restrict__ vals, int* __restrict__ cursor,
                          int* __restrict__ ecol, float* __restrict__ eval) {
    int e = blockIdx.x * blockDim.x + threadIdx.x;
    if (e < EE) {
        int p = atomicAdd(&cursor[rows[e]], 1);
        ecol[p] = cols[e];
        eval[p] = vals[e];
    }
}

// ---- weights: Bt[n][s*D+k] = combined W, transposed, split to bf16 hi/lo ----
__global__ void k_prep_bt(const float* __restrict__ Wa, const float* __restrict__ Wb,
                          __nv_bfloat16* __restrict__ Bth, __nv_bfloat16* __restrict__ Btl,
                          int D) {
    int K = 4 * D;
    int idx = blockIdx.x * blockDim.x + threadIdx.x;
    if (idx >= 256 * K) return;
    int n = idx / K;
    int t = idx - n * K;
    int s = t / D;
    int k = t - s * D;
    const float* W = (n < 128) ? Wa : Wb;
    int j = n & 127;
    int sz = D * 128;
    float v;
    if (s == 0) v = W[k * 128 + j] + W[sz + k * 128 + j] + W[2 * sz + k * 128 + j];
    else        v = W[(s + 2) * sz + k * 128 + j];
    __nv_bfloat16 hi, lo;
    split_bf16(v, hi, lo);
    Bth[idx] = hi;
    Btl[idx] = lo;
}

// ---- split x (N, D) fp32 -> bf16 hi/lo into slice (stride Kstr) ----
__global__ void k_split_x(const float4* __restrict__ x, __nv_bfloat16* __restrict__ xh,
                          __nv_bfloat16* __restrict__ xl, int DQ, int Kstr, int total) {
    int i = blockIdx.x * blockDim.x + threadIdx.x;
    if (i >= total) return;
    int r = i / DQ, c4 = i - r * DQ;
    float4 v = x[i];
    union { __nv_bfloat16 b[4]; uint2 u; } H, L;
    split_bf16(v.x, H.b[0], L.b[0]);
    split_bf16(v.y, H.b[1], L.b[1]);
    split_bf16(v.z, H.b[2], L.b[2]);
    split_bf16(v.w, H.b[3], L.b[3]);
    size_t o = (size_t)r * Kstr + c4 * 4;
    *(uint2*)&xh[o] = H.u;
    *(uint2*)&xl[o] = L.u;
}

// ---------------- SPMM (vectorized) + optional bf16 split output ----------------
template <int DQ, int RPB, bool WB>
__global__ void k_spmm_v(const float4* __restrict__ x, float4* __restrict__ y,
                         const int* __restrict__ rowptr, const int* __restrict__ ecol,
                         const float* __restrict__ eval,
                         __nv_bfloat16* __restrict__ yh, __nv_bfloat16* __restrict__ yl,
                         int Kstr) {
    int rl = threadIdx.x / DQ;
    int f = threadIdx.x % DQ;
    int r = blockIdx.x * RPB + rl;
    if (r >= NN) return;
    int s = __ldg(&rowptr[r]);
    int e = __ldg(&rowptr[r + 1]);
    float4 acc = make_float4(0.f, 0.f, 0.f, 0.f);
    int j = s;
    for (; j + 4 <= e; j += 4) {
        int c0 = __ldg(&ecol[j]);
        int c1 = __ldg(&ecol[j + 1]);
        int c2 = __ldg(&ecol[j + 2]);
        int c3 = __ldg(&ecol[j + 3]);
        float v0 = __ldg(&eval[j]);
        float v1 = __ldg(&eval[j + 1]);
        float v2 = __ldg(&eval[j + 2]);
        float v3 = __ldg(&eval[j + 3]);
        float4 x0 = __ldg(&x[(size_t)c0 * DQ + f]);
        float4 x1 = __ldg(&x[(size_t)c1 * DQ + f]);
        float4 x2 = __ldg(&x[(size_t)c2 * DQ + f]);
        float4 x3 = __ldg(&x[(size_t)c3 * DQ + f]);
        acc.x = fmaf(v0, x0.x, acc.x); acc.y = fmaf(v0, x0.y, acc.y);
        acc.z = fmaf(v0, x0.z, acc.z); acc.w = fmaf(v0, x0.w, acc.w);
        acc.x = fmaf(v1, x1.x, acc.x); acc.y = fmaf(v1, x1.y, acc.y);
        acc.z = fmaf(v1, x1.z, acc.z); acc.w = fmaf(v1, x1.w, acc.w);
        acc.x = fmaf(v2, x2.x, acc.x); acc.y = fmaf(v2, x2.y, acc.y);
        acc.z = fmaf(v2, x2.z, acc.z); acc.w = fmaf(v2, x2.w, acc.w);
        acc.x = fmaf(v3, x3.x, acc.x); acc.y = fmaf(v3, x3.y, acc.y);
        acc.z = fmaf(v3, x3.z, acc.z); acc.w = fmaf(v3, x3.w, acc.w);
    }
    for (; j < e; j++) {
        int c = __ldg(&ecol[j]);
        float v = __ldg(&eval[j]);
        float4 xv = __ldg(&x[(size_t)c * DQ + f]);
        acc.x = fmaf(v, xv.x, acc.x); acc.y = fmaf(v, xv.y, acc.y);
        acc.z = fmaf(v, xv.z, acc.z); acc.w = fmaf(v, xv.w, acc.w);
    }
    y[(size_t)r * DQ + f] = acc;
    if (WB) {
        union { __nv_bfloat16 b[4]; uint2 u; } H, L;
        split_bf16(acc.x, H.b[0], L.b[0]);
        split_bf16(acc.y, H.b[1], L.b[1]);
        split_bf16(acc.z, H.b[2], L.b[2]);
        split_bf16(acc.w, H.b[3], L.b[3]);
        size_t o = (size_t)r * Kstr + f * 4;
        *(uint2*)&yh[o] = H.u;
        *(uint2*)&yl[o] = L.u;
    }
}

// ================= warp-MMA GEMM (mma.sync bf16, 3-term compensated) =================
// C(Nrows,256) = Xh@Bh^T + Xh@Bl^T + Xl@Bh^T ; relu on col-block 0
// Xh/Xl: (Nrows, K) bf16 row-major. Bh/Bl: (256, K) bf16 row-major.
// CTA tile 128x128, 8 warps (4M x 2N), warp tile 32x64, K-chunk 64.
// smem tiles 128 rows x 64 bf16, padded row stride 144B (conflict-free ldmatrix).
#define TILE_B 18432
#define GSM (4 * TILE_B)
__global__ __launch_bounds__(256)
void k_gemm_mma(const __nv_bfloat16* __restrict__ Xh, const __nv_bfloat16* __restrict__ Xl,
                const __nv_bfloat16* __restrict__ Bh, const __nv_bfloat16* __restrict__ Bl,
                float* __restrict__ C, int K, int Nrows) {
    extern __shared__ char smem[];
    const uint32_t sb = smem_to_u32(smem);
    const int tid = threadIdx.x;
    const int lane = tid & 31;
    const int wid = tid >> 5;
    const int warpM = (wid & 3) * 32;
    const int warpN = (wid >> 2) * 64;
    const int blockRow = blockIdx.x * 128;
    const int nBase = blockIdx.y * 128;

    const uint32_t sAh = sb;
    const uint32_t sAl = sb + TILE_B;
    const uint32_t sBh = sb + 2 * TILE_B;
    const uint32_t sBl = sb + 3 * TILE_B;

    float acc[2][8][4];
#pragma unroll
    for (int i = 0; i < 2; i++)
#pragma unroll
        for (int j = 0; j < 8; j++)
#pragma unroll
            for (int q = 0; q < 4; q++) acc[i][j][q] = 0.f;

    const int lrow = lane & 7;
    const int lsel = lane >> 3;
    // ldmatrix lane offsets (A: matrices m0/m1/k-hi m0/m1; B: n0/k-hi/n+8/n+8 k-hi)
    const uint32_t aoff = (uint32_t)((lrow + ((lsel & 1) ? 8 : 0)) * 144 + ((lsel >> 1) ? 16 : 0));
    const uint32_t boff = (uint32_t)((lrow + ((lsel >> 1) ? 8 : 0)) * 144 + ((lsel & 1) ? 16 : 0));

    for (int kb = 0; kb < K; kb += 64) {
        // ---- load 4 tiles (Ah, Al, Bh, Bl): 128x64 bf16 each ----
#pragma unroll
        for (int it = 0; it < 4; ++it) {
            int u = tid + it * 256;
            int row = u >> 3, seg = u & 7;
            uint32_t so = (uint32_t)(row * 144 + seg * 16);
            size_t giA = (size_t)(blockRow + row) * K + kb + seg * 8;
            uint4 vh = make_uint4(0u, 0u, 0u, 0u), vl = make_uint4(0u, 0u, 0u, 0u);
            if (blockRow + row < Nrows) {
                vh = *(const uint4*)&Xh[giA];
                vl = *(const uint4*)&Xl[giA];
            }
            *(uint4*)(smem + so) = vh;
            *(uint4*)(smem + TILE_B + so) = vl;
            size_t giB = (size_t)(nBase + row) * K + kb + seg * 8;
            *(uint4*)(smem + 2 * TILE_B + so) = *(const uint4*)&Bh[giB];
            *(uint4*)(smem + 3 * TILE_B + so) = *(const uint4*)&Bl[giB];
        }
        __syncthreads();
#pragma unroll
        for (int ks = 0; ks < 4; ++ks) {
            uint32_t kByte = ks * 32;
            uint32_t ah[2][4], al[2][4], bhf[4][4], blf[4][4];
#pragma unroll
            for (int i = 0; i < 2; i++) {
                uint32_t ab = (uint32_t)((warpM + i * 16) * 144) + kByte;
                ldsm4(ah[i], sAh + ab + aoff);
                ldsm4(al[i], sAl + ab + aoff);
            }
#pragma unroll
            for (int j = 0; j < 4; j++) {
                uint32_t bb = (uint32_t)((warpN + j * 16) * 144) + kByte;
                ldsm4(bhf[j], sBh + bb + boff);
                ldsm4(blf[j], sBl + bb + boff);
            }
#pragma unroll
            for (int i = 0; i < 2; i++)
#pragma unroll
                for (int j = 0; j < 8; j++) {
                    const uint32_t* bph = &bhf[j >> 1][(j & 1) * 2];
                    const uint32_t* bpl = &blf[j >> 1][(j & 1) * 2];
                    mma16816(acc[i][j], ah[i], bph);
                    mma16816(acc[i][j], ah[i], bpl);
                    mma16816(acc[i][j], al[i], bph);
                }
        }
        __syncthreads();
    }

    // ---- epilogue ----
    const bool doRelu = (blockIdx.y == 0);
    int g = lane >> 2;
    int cq = (lane & 3) * 2;
#pragma unroll
    for (int i = 0; i < 2; i++) {
        int r0 = blockRow + warpM + i * 16 + g;
#pragma unroll
        for (int j = 0; j < 8; j++) {
            int col = nBase + warpN + j * 8 + cq;
            float2 v0 = make_float2(acc[i][j][0], acc[i][j][1]);
            float2 v1 = make_float2(acc[i][j][2], acc[i][j][3]);
            if (doRelu) {
                v0.x = fmaxf(v0.x, 0.f); v0.y = fmaxf(v0.y, 0.f);
                v1.x = fmaxf(v1.x, 0.f); v1.y = fmaxf(v1.y, 0.f);
            }
            if (r0 < Nrows) *(float2*)&C[(size_t)r0 * 256 + col] = v0;
            if (r0 + 8 < Nrows) *(float2*)&C[(size_t)(r0 + 8) * 256 + col] = v1;
        }
    }
}

// ---------------- BatchNorm ----------------
__global__ void k_bn_stats(const float* __restrict__ h, float* __restrict__ psum,
                           float* __restrict__ psq, int Nrows) {
    int f = threadIdx.x;
    float s = 0.f, q = 0.f;
    for (int r = blockIdx.x; r < Nrows; r += gridDim.x) {
        float v = h[(size_t)r * 256 + f];
        s += v;
        q += v * v;
    }
    psum[blockIdx.x * 256 + f] = s;
    psq[blockIdx.x * 256 + f] = q;
}

__global__ void k_bn_reduce(const float* __restrict__ psum, const float* __restrict__ psq,
                            const float* __restrict__ bnp, float* __restrict__ scale,
                            float* __restrict__ shift) {
    int f = threadIdx.x;
    double s = 0.0, q = 0.0;
    for (int b = 0; b < 256; b++) {
        s += (double)psum[b * 256 + f];
        q += (double)psq[b * 256 + f];
    }
    double mu = s / (double)NN;
    double var = q / (double)NN - mu * mu;
    float g, bt;
    if (f < 128) { g = bnp[f];             bt = bnp[128 + f]; }
    else         { g = bnp[256 + f - 128]; bt = bnp[384 + f - 128]; }
    float sc = g * rsqrtf((float)var + BN_EPS);
    scale[f] = sc;
    shift[f] = bt - (float)mu * sc;
}

// apply BN in place; optionally also emit bf16 split into slice (stride Kstr)
template <bool WB>
__global__ void k_bn_apply(float4* __restrict__ h, const float* __restrict__ scale,
                           const float* __restrict__ shift,
                           __nv_bfloat16* __restrict__ xh, __nv_bfloat16* __restrict__ xl,
                           int Kstr) {
    int i = blockIdx.x * blockDim.x + threadIdx.x;  // NN*64 float4s
    if (i >= NN * 64) return;
    int c = (i & 63) * 4;
    float4 v = h[i];
    v.x = fmaf(v.x, scale[c + 0], shift[c + 0]);
    v.y = fmaf(v.y, scale[c + 1], shift[c + 1]);
    v.z = fmaf(v.z, scale[c + 2], shift[c + 2]);
    v.w = fmaf(v.w, scale[c + 3], shift[c + 3]);
    h[i] = v;
    if (WB) {
        int r = i >> 6;
        union { __nv_bfloat16 b[4]; uint2 u; } H, L;
        split_bf16(v.x, H.b[0], L.b[0]);
        split_bf16(v.y, H.b[1], L.b[1]);
        split_bf16(v.z, H.b[2], L.b[2]);
        split_bf16(v.w, H.b[3], L.b[3]);
        size_t o = (size_t)r * Kstr + c;
        *(uint2*)&xh[o] = H.u;
        *(uint2*)&xl[o] = L.u;
    }
}

// ---------------- z = h2 @ We + be ----------------
__global__ void k_zproj(const float* __restrict__ h, const float* __restrict__ We,
                        const float* __restrict__ be, float* __restrict__ z) {
    __shared__ float Ws[256 * 16];
    for (int i = threadIdx.x; i < 4096; i += blockDim.x) Ws[i] = We[i];
    __syncthreads();
    int t = blockIdx.x * blockDim.x + threadIdx.x;
    int r = t >> 4, m = t & 15;
    float acc = __ldg(&be[m]);
    const float4* hp = (const float4*)(h + (size_t)r * 256);
#pragma unroll 4
    for (int k4 = 0; k4 < 64; k4++) {
        float4 hv = hp[k4];
        int k = k4 * 4;
        acc += hv.x * Ws[k * 16 + m] + hv.y * Ws[(k + 1) * 16 + m] +
               hv.z * Ws[(k + 2) * 16 + m] + hv.w * Ws[(k + 3) * 16 + m];
    }
    z[t] = acc;
}

// ---------------- per-edge score + softmax over 16 machines ----------------
__global__ void k_edge(const int* __restrict__ rows, const int* __restrict__ cols,
                       const float* __restrict__ vals, const float* __restrict__ z,
                       float* __restrict__ out) {
    int idx = blockIdx.x * blockDim.x + threadIdx.x;
    int e = idx >> 4, m = idx & 15;
    int r = __ldg(&rows[e]);
    int c = __ldg(&cols[e]);
    float s = __ldg(&vals[e]) * (__ldg(&z[r * 16 + m]) + __ldg(&z[c * 16 + m]));
    float mx = s;
#pragma unroll
    for (int off = 8; off > 0; off >>= 1)
        mx = fmaxf(mx, __shfl_xor_sync(0xffffffffu, mx, off, 16));
    float ex = __expf(s - mx);
    float sm = ex;
#pragma unroll
    for (int off = 8; off > 0; off >>= 1)
        sm += __shfl_xor_sync(0xffffffffu, sm, off, 16);
    out[idx] = ex / sm;
}

// ---------------- launch ----------------
extern "C" void kernel_launch(void* const* d_in, const int* in_sizes, int n_in,
                              void* d_out, int out_size) {
    const float* x    = (const float*)d_in[0];
    const int*   rows = (const int*)d_in[1];
    const int*   cols = (const int*)d_in[2];
    const float* vals = (const float*)d_in[3];
    const float* l0Wa = (const float*)d_in[4];
    const float* l0Wb = (const float*)d_in[5];
    const float* l0bn = (const float*)d_in[6];
    const float* l1Wa = (const float*)d_in[7];
    const float* l1Wb = (const float*)d_in[8];
    const float* l1bn = (const float*)d_in[9];
    const float* We   = (const float*)d_in[10];
    const float* be   = (const float*)d_in[11];
    float* out = (float*)d_out;

    float *a0, *a1, *a2, *tmp, *h, *h2, *z, *evalp, *psum, *psq, *scale, *shift;
    int *rowptr, *cnt, *cursor, *ecol;
    __nv_bfloat16 *X0h, *X0l, *X1h, *X1l, *Bt0h, *Bt0l, *Bt1h, *Bt1l;
    cudaGetSymbolAddress((void**)&a0, g_a0);
    cudaGetSymbolAddress((void**)&a1, g_a1);
    cudaGetSymbolAddress((void**)&a2, g_a2);
    cudaGetSymbolAddress((void**)&tmp, g_tmp);
    cudaGetSymbolAddress((void**)&h, g_h);
    cudaGetSymbolAddress((void**)&h2, g_h2);
    cudaGetSymbolAddress((void**)&z, g_z);
    cudaGetSymbolAddress((void**)&evalp, g_eval);
    cudaGetSymbolAddress((void**)&psum, g_psum);
    cudaGetSymbolAddress((void**)&psq, g_psq);
    cudaGetSymbolAddress((void**)&scale, g_scale);
    cudaGetSymbolAddress((void**)&shift, g_shift);
    cudaGetSymbolAddress((void**)&rowptr, g_rowptr);
    cudaGetSymbolAddress((void**)&cnt, g_cnt);
    cudaGetSymbolAddress((void**)&cursor, g_cursor);
    cudaGetSymbolAddress((void**)&ecol, g_ecol);
    cudaGetSymbolAddress((void**)&X0h, g_X0h);
    cudaGetSymbolAddress((void**)&X0l, g_X0l);
    cudaGetSymbolAddress((void**)&X1h, g_X1h);
    cudaGetSymbolAddress((void**)&X1l, g_X1l);
    cudaGetSymbolAddress((void**)&Bt0h, g_Bt0h);
    cudaGetSymbolAddress((void**)&Bt0l, g_Bt0l);
    cudaGetSymbolAddress((void**)&Bt1h, g_Bt1h);
    cudaGetSymbolAddress((void**)&Bt1l, g_Bt1l);

    cudaFuncSetAttribute(k_gemm_mma, cudaFuncAttributeMaxDynamicSharedMemorySize, GSM);

    // ---- CSR build ----
    k_zero_int<<<(NN + 255) / 256, 256>>>(cnt, NN);
    k_hist<<<(EE + 255) / 256, 256>>>(rows, cnt);
    k_scan<<<1, 1024>>>(cnt, rowptr);
    k_copy_int<<<(NN + 255) / 256, 256>>>(rowptr, cursor, NN);
    k_scatter<<<(EE + 255) / 256, 256>>>(rows, cols, vals, cursor, ecol, evalp);

    // ---- combined transposed weights (bf16 hi/lo) ----
    k_prep_bt<<<(256 * 512 + 255) / 256, 256>>>(l0Wa, l0Wb, Bt0h, Bt0l, 128);
    k_prep_bt<<<(256 * 1024 + 255) / 256, 256>>>(l1Wa, l1Wb, Bt1h, Bt1l, 256);

    dim3 ggrid((NN + 127) / 128, 2);

    // ---- layer 0 (K = 512; slices at cols 0,128,256,384) ----
    k_split_x<<<(NN * 32 + 255) / 256, 256>>>((const float4*)x, X0h, X0l, 32, 512, NN * 32);
    k_spmm_v<32, 4, true><<<(NN + 3) / 4, 128>>>((const float4*)x, (float4*)a0, rowptr, ecol, evalp, X0h + 128, X0l + 128, 512);
    k_spmm_v<32, 4, true><<<(NN + 3) / 4, 128>>>((const float4*)a0, (float4*)a1, rowptr, ecol, evalp, X0h + 256, X0l + 256, 512);
    k_spmm_v<32, 4, false><<<(NN + 3) / 4, 128>>>((const float4*)a1, (float4*)tmp, rowptr, ecol, evalp, nullptr, nullptr, 0);
    k_spmm_v<32, 4, true><<<(NN + 3) / 4, 128>>>((const float4*)tmp, (float4*)a2, rowptr, ecol, evalp, X0h + 384, X0l + 384, 512);
    k_gemm_mma<<<ggrid, 256, GSM>>>(X0h, X0l, Bt0h, Bt0l, h, 512, NN);
    k_bn_stats<<<256, 256>>>(h, psum, psq, NN);
    k_bn_reduce<<<1, 256>>>(psum, psq, l0bn, scale, shift);
    k_bn_apply<true><<<(NN * 64 + 255) / 256, 256>>>((float4*)h, scale, shift, X1h, X1l, 1024);

    // ---- layer 1 (K = 1024; slices at cols 0,256,512,768) ----
    k_spmm_v<64, 2, true><<<(NN + 1) / 2, 128>>>((const float4*)h, (float4*)a0, rowptr, ecol, evalp, X1h + 256, X1l + 256, 1024);
    k_spmm_v<64, 2, true><<<(NN + 1) / 2, 128>>>((const float4*)a0, (float4*)a1, rowptr, ecol, evalp, X1h + 512, X1l + 512, 1024);
    k_spmm_v<64, 2, false><<<(NN + 1) / 2, 128>>>((const float4*)a1, (float4*)tmp, rowptr, ecol, evalp, nullptr, nullptr, 0);
    k_spmm_v<64, 2, true><<<(NN + 1) / 2, 128>>>((const float4*)tmp, (float4*)a2, rowptr, ecol, evalp, X1h + 768, X1l + 768, 1024);
    k_gemm_mma<<<ggrid, 256, GSM>>>(X1h, X1l, Bt1h, Bt1l, h2, 1024, NN);
    k_bn_stats<<<256, 256>>>(h2, psum, psq, NN);
    k_bn_reduce<<<1, 256>>>(psum, psq, l1bn, scale, shift);
    k_bn_apply<false><<<(NN * 64 + 255) / 256, 256>>>((float4*)h2, scale, shift, nullptr, nullptr, 0);

    // ---- final projection + per-edge softmax ----
    k_zproj<<<(NN * 16) / 256, 256>>>(h2, We, be, z);
    k_edge<<<(EE * 16) / 256, 256>>>(rows, cols, vals, z, out);
}

// round 8
// speedup vs baseline: 1.7370x; 1.0723x over previous
#include <cuda_runtime.h>
#include <cuda_bf16.h>
#include <cuda_fp16.h>
#include <math.h>
#include <stdint.h>

#define NN 50000
#define EE 800000
#define BN_EPS 1e-3f

// ---------------- scratch (device globals; no allocation allowed) ----------------
__device__ float g_h[NN * 256];
__device__ float g_h2[NN * 256];
__device__ float g_z[NN * 16];
__device__ int   g_rowptr[NN + 1];
__device__ int   g_cnt[NN];
__device__ int   g_cursor[NN];
__device__ int   g_ecol[EE];
__device__ float g_eval[EE];
__device__ float g_psum[256 * 256];
__device__ float g_psq[256 * 256];
__device__ float g_scale[256];
__device__ float g_shift[256];
// fp16 hop-feature buffers (ping-pong chain; width <= 256)
__device__ __half g_f16x[(size_t)NN * 256];
__device__ __half g_f16a[(size_t)NN * 256];
__device__ __half g_f16b[(size_t)NN * 256];
__device__ __half g_f16c[(size_t)NN * 256];
// bf16 hi/lo feature buffers (concatenated hop features for GEMM)
__device__ __nv_bfloat16 g_X0h[NN * 512];
__device__ __nv_bfloat16 g_X0l[NN * 512];
__device__ __nv_bfloat16 g_X1h[(size_t)NN * 1024];
__device__ __nv_bfloat16 g_X1l[(size_t)NN * 1024];
// transposed combined weights (256, K) bf16 hi/lo
__device__ __nv_bfloat16 g_Bt0h[256 * 512];
__device__ __nv_bfloat16 g_Bt0l[256 * 512];
__device__ __nv_bfloat16 g_Bt1h[256 * 1024];
__device__ __nv_bfloat16 g_Bt1l[256 * 1024];

// ---------------- helpers ----------------
__device__ __forceinline__ uint32_t smem_to_u32(const void* p) {
    uint32_t a;
    asm("{ .reg .u64 t; cvta.to.shared.u64 t, %1; cvt.u32.u64 %0, t; }" : "=r"(a) : "l"(p));
    return a;
}
__device__ __forceinline__ void ldsm4(uint32_t* r, uint32_t addr) {
    asm volatile("ldmatrix.sync.aligned.m8n8.x4.shared.b16 {%0,%1,%2,%3}, [%4];"
                 : "=r"(r[0]), "=r"(r[1]), "=r"(r[2]), "=r"(r[3]) : "r"(addr));
}
__device__ __forceinline__ void mma16816(float* c, const uint32_t* a, const uint32_t* b) {
    asm volatile(
        "mma.sync.aligned.m16n8k16.row.col.f32.bf16.bf16.f32 "
        "{%0,%1,%2,%3}, {%4,%5,%6,%7}, {%8,%9}, {%0,%1,%2,%3};"
        : "+f"(c[0]), "+f"(c[1]), "+f"(c[2]), "+f"(c[3])
        : "r"(a[0]), "r"(a[1]), "r"(a[2]), "r"(a[3]), "r"(b[0]), "r"(b[1]));
}
__device__ __forceinline__ void split_bf16(float v, __nv_bfloat16& hi, __nv_bfloat16& lo) {
    hi = __float2bfloat16(v);
    lo = __float2bfloat16(v - __bfloat162float(hi));
}
__device__ __forceinline__ void accum8(float* acc, uint4 u, float v) {
    float2 f0 = __half22float2(*(__half2*)&u.x);
    float2 f1 = __half22float2(*(__half2*)&u.y);
    float2 f2 = __half22float2(*(__half2*)&u.z);
    float2 f3 = __half22float2(*(__half2*)&u.w);
    acc[0] = fmaf(v, f0.x, acc[0]); acc[1] = fmaf(v, f0.y, acc[1]);
    acc[2] = fmaf(v, f1.x, acc[2]); acc[3] = fmaf(v, f1.y, acc[3]);
    acc[4] = fmaf(v, f2.x, acc[4]); acc[5] = fmaf(v, f2.y, acc[5]);
    acc[6] = fmaf(v, f3.x, acc[6]); acc[7] = fmaf(v, f3.y, acc[7]);
}

// ---------------- CSR build ----------------
__global__ void k_zero_int(int* __restrict__ p, int n) {
    int i = blockIdx.x * blockDim.x + threadIdx.x;
    if (i < n) p[i] = 0;
}
__global__ void k_hist(const int* __restrict__ rows, int* __restrict__ cnt) {
    int e = blockIdx.x * blockDim.x + threadIdx.x;
    if (e < EE) atomicAdd(&cnt[rows[e]], 1);
}
__global__ void k_scan(const int* __restrict__ cnt, int* __restrict__ rowptr) {
    __shared__ int ss[1024];
    int t = threadIdx.x;
    const int chunk = (NN + 1023) / 1024;
    int b = t * chunk;
    int e = min(b + chunk, NN);
    int s = 0;
    for (int i = b; i < e; i++) s += cnt[i];
    ss[t] = s;
    __syncthreads();
    for (int off = 1; off < 1024; off <<= 1) {
        int v = (t >= off) ? ss[t - off] : 0;
        __syncthreads();
        ss[t] += v;
        __syncthreads();
    }
    int run = (t == 0) ? 0 : ss[t - 1];
    for (int i = b; i < e; i++) { rowptr[i] = run; run += cnt[i]; }
    if (t == 1023) rowptr[NN] = ss[1023];
}
__global__ void k_copy_int(const int* __restrict__ a, int* __restrict__ b, int n) {
    int i = blockIdx.x * blockDim.x + threadIdx.x;
    if (i < n) b[i] = a[i];
}
__global__ void k_scatter(const int* __restrict__ rows, const int* __restrict__ cols,
                          const float* __restrict__ vals, int* __restrict__ cursor,
                          int* __restrict__ ecol, float* __restrict__ eval) {
    int e = blockIdx.x * blockDim.x + threadIdx.x;
    if (e < EE) {
        int p = atomicAdd(&cursor[rows[e]], 1);
        ecol[p] = cols[e];
        eval[p] = vals[e];
    }
}

// ---- weights: Bt[n][s*D+k] = combined W, transposed, split to bf16 hi/lo ----
__global__ void k_prep_bt(const float* __restrict__ Wa, const float* __restrict__ Wb,
                          __nv_bfloat16* __restrict__ Bth, __nv_bfloat16* __restrict__ Btl,
                          int D) {
    int K = 4 * D;
    int idx = blockIdx.x * blockDim.x + threadIdx.x;
    if (idx >= 256 * K) return;
    int n = idx / K;
    int t = idx - n * K;
    int s = t / D;
    int k = t - s * D;
    const float* W = (n < 128) ? Wa : Wb;
    int j = n & 127;
    int sz = D * 128;
    float v;
    if (s == 0) v = W[k * 128 + j] + W[sz + k * 128 + j] + W[2 * sz + k * 128 + j];
    else        v = W[(s + 2) * sz + k * 128 + j];
    __nv_bfloat16 hi, lo;
    split_bf16(v, hi, lo);
    Bth[idx] = hi;
    Btl[idx] = lo;
}

// ---- split x (N, D) fp32 -> bf16 hi/lo slice (stride Kstr) + fp16 copy ----
__global__ void k_split_x(const float4* __restrict__ x, __nv_bfloat16* __restrict__ xh,
                          __nv_bfloat16* __restrict__ xl, __half* __restrict__ xf,
                          int DQ, int Kstr, int total) {
    int i = blockIdx.x * blockDim.x + threadIdx.x;
    if (i >= total) return;
    int r = i / DQ, c4 = i - r * DQ;
    float4 v = x[i];
    union { __nv_bfloat16 b[4]; uint2 u; } H, L;
    split_bf16(v.x, H.b[0], L.b[0]);
    split_bf16(v.y, H.b[1], L.b[1]);
    split_bf16(v.z, H.b[2], L.b[2]);
    split_bf16(v.w, H.b[3], L.b[3]);
    size_t o = (size_t)r * Kstr + c4 * 4;
    *(uint2*)&xh[o] = H.u;
    *(uint2*)&xl[o] = L.u;
    union { __half h[4]; uint2 u; } F;
    F.h[0] = __float2half_rn(v.x);
    F.h[1] = __float2half_rn(v.y);
    F.h[2] = __float2half_rn(v.z);
    F.h[3] = __float2half_rn(v.w);
    *(uint2*)&xf[(size_t)r * (DQ * 4) + c4 * 4] = F.u;
}

// ---------------- SPMM over fp16 features, fp32 accumulate ----------------
// CQ = D/8 (uint4 chunks of 8 halves). WMODE: 0 = f16 out only, 1 = f16 + bf16 hi/lo,
// 2 = bf16 hi/lo only (last hop).
template <int CQ, int RPB, int WMODE>
__global__ void k_spmm_h(const uint4* __restrict__ x, uint4* __restrict__ yf,
                         const int* __restrict__ rowptr, const int* __restrict__ ecol,
                         const float* __restrict__ eval,
                         __nv_bfloat16* __restrict__ yh, __nv_bfloat16* __restrict__ yl,
                         int Kstr) {
    int rl = threadIdx.x / CQ;
    int f = threadIdx.x % CQ;
    int r = blockIdx.x * RPB + rl;
    if (r >= NN) return;
    int s = __ldg(&rowptr[r]);
    int e = __ldg(&rowptr[r + 1]);
    float acc[8];
#pragma unroll
    for (int q = 0; q < 8; q++) acc[q] = 0.f;
    int j = s;
    for (; j + 4 <= e; j += 4) {
        int c0 = __ldg(&ecol[j]);     float v0 = __ldg(&eval[j]);
        int c1 = __ldg(&ecol[j + 1]); float v1 = __ldg(&eval[j + 1]);
        int c2 = __ldg(&ecol[j + 2]); float v2 = __ldg(&eval[j + 2]);
        int c3 = __ldg(&ecol[j + 3]); float v3 = __ldg(&eval[j + 3]);
        uint4 u0 = __ldg(&x[(size_t)c0 * CQ + f]);
        uint4 u1 = __ldg(&x[(size_t)c1 * CQ + f]);
        uint4 u2 = __ldg(&x[(size_t)c2 * CQ + f]);
        uint4 u3 = __ldg(&x[(size_t)c3 * CQ + f]);
        accum8(acc, u0, v0);
        accum8(acc, u1, v1);
        accum8(acc, u2, v2);
        accum8(acc, u3, v3);
    }
    for (; j < e; j++) {
        int c = __ldg(&ecol[j]);
        float v = __ldg(&eval[j]);
        accum8(acc, __ldg(&x[(size_t)c * CQ + f]), v);
    }
    if (WMODE != 2) {
        union { __half2 h[4]; uint4 u; } F;
        F.h[0] = __floats2half2_rn(acc[0], acc[1]);
        F.h[1] = __floats2half2_rn(acc[2], acc[3]);
        F.h[2] = __floats2half2_rn(acc[4], acc[5]);
        F.h[3] = __floats2half2_rn(acc[6], acc[7]);
        yf[(size_t)r * CQ + f] = F.u;
    }
    if (WMODE != 0) {
        union { __nv_bfloat16 b[8]; uint4 u; } H, L;
#pragma unroll
        for (int q = 0; q < 8; q++) split_bf16(acc[q], H.b[q], L.b[q]);
        size_t o = (size_t)r * Kstr + f * 8;
        *(uint4*)&yh[o] = H.u;
        *(uint4*)&yl[o] = L.u;
    }
}

// ================= warp-MMA GEMM (mma.sync bf16, 3-term compensated) =================
// C(Nrows,256) = Xh@Bh^T + Xh@Bl^T + Xl@Bh^T ; relu on col-block 0
#define TILE_B 18432
#define GSM (4 * TILE_B)
__global__ __launch_bounds__(256)
void k_gemm_mma(const __nv_bfloat16* __restrict__ Xh, const __nv_bfloat16* __restrict__ Xl,
                const __nv_bfloat16* __restrict__ Bh, const __nv_bfloat16* __restrict__ Bl,
                float* __restrict__ C, int K, int Nrows) {
    extern __shared__ char smem[];
    const uint32_t sb = smem_to_u32(smem);
    const int tid = threadIdx.x;
    const int lane = tid & 31;
    const int wid = tid >> 5;
    const int warpM = (wid & 3) * 32;
    const int warpN = (wid >> 2) * 64;
    const int blockRow = blockIdx.x * 128;
    const int nBase = blockIdx.y * 128;

    const uint32_t sAh = sb;
    const uint32_t sAl = sb + TILE_B;
    const uint32_t sBh = sb + 2 * TILE_B;
    const uint32_t sBl = sb + 3 * TILE_B;

    float acc[2][8][4];
#pragma unroll
    for (int i = 0; i < 2; i++)
#pragma unroll
        for (int j = 0; j < 8; j++)
#pragma unroll
            for (int q = 0; q < 4; q++) acc[i][j][q] = 0.f;

    const int lrow = lane & 7;
    const int lsel = lane >> 3;
    const uint32_t aoff = (uint32_t)((lrow + ((lsel & 1) ? 8 : 0)) * 144 + ((lsel >> 1) ? 16 : 0));
    const uint32_t boff = (uint32_t)((lrow + ((lsel >> 1) ? 8 : 0)) * 144 + ((lsel & 1) ? 16 : 0));

    for (int kb = 0; kb < K; kb += 64) {
#pragma unroll
        for (int it = 0; it < 4; ++it) {
            int u = tid + it * 256;
            int row = u >> 3, seg = u & 7;
            uint32_t so = (uint32_t)(row * 144 + seg * 16);
            size_t giA = (size_t)(blockRow + row) * K + kb + seg * 8;
            uint4 vh = make_uint4(0u, 0u, 0u, 0u), vl = make_uint4(0u, 0u, 0u, 0u);
            if (blockRow + row < Nrows) {
                vh = *(const uint4*)&Xh[giA];
                vl = *(const uint4*)&Xl[giA];
            }
            *(uint4*)(smem + so) = vh;
            *(uint4*)(smem + TILE_B + so) = vl;
            size_t giB = (size_t)(nBase + row) * K + kb + seg * 8;
            *(uint4*)(smem + 2 * TILE_B + so) = *(const uint4*)&Bh[giB];
            *(uint4*)(smem + 3 * TILE_B + so) = *(const uint4*)&Bl[giB];
        }
        __syncthreads();
#pragma unroll
        for (int ks = 0; ks < 4; ++ks) {
            uint32_t kByte = ks * 32;
            uint32_t ah[2][4], al[2][4], bhf[4][4], blf[4][4];
#pragma unroll
            for (int i = 0; i < 2; i++) {
                uint32_t ab = (uint32_t)((warpM + i * 16) * 144) + kByte;
                ldsm4(ah[i], sAh + ab + aoff);
                ldsm4(al[i], sAl + ab + aoff);
            }
#pragma unroll
            for (int j = 0; j < 4; j++) {
                uint32_t bb = (uint32_t)((warpN + j * 16) * 144) + kByte;
                ldsm4(bhf[j], sBh + bb + boff);
                ldsm4(blf[j], sBl + bb + boff);
            }
#pragma unroll
            for (int i = 0; i < 2; i++)
#pragma unroll
                for (int j = 0; j < 8; j++) {
                    const uint32_t* bph = &bhf[j >> 1][(j & 1) * 2];
                    const uint32_t* bpl = &blf[j >> 1][(j & 1) * 2];
                    mma16816(acc[i][j], ah[i], bph);
                    mma16816(acc[i][j], ah[i], bpl);
                    mma16816(acc[i][j], al[i], bph);
                }
        }
        __syncthreads();
    }

    const bool doRelu = (blockIdx.y == 0);
    int g = lane >> 2;
    int cq = (lane & 3) * 2;
#pragma unroll
    for (int i = 0; i < 2; i++) {
        int r0 = blockRow + warpM + i * 16 + g;
#pragma unroll
        for (int j = 0; j < 8; j++) {
            int col = nBase + warpN + j * 8 + cq;
            float2 v0 = make_float2(acc[i][j][0], acc[i][j][1]);
            float2 v1 = make_float2(acc[i][j][2], acc[i][j][3]);
            if (doRelu) {
                v0.x = fmaxf(v0.x, 0.f); v0.y = fmaxf(v0.y, 0.f);
                v1.x = fmaxf(v1.x, 0.f); v1.y = fmaxf(v1.y, 0.f);
            }
            if (r0 < Nrows) *(float2*)&C[(size_t)r0 * 256 + col] = v0;
            if (r0 + 8 < Nrows) *(float2*)&C[(size_t)(r0 + 8) * 256 + col] = v1;
        }
    }
}

// ---------------- BatchNorm ----------------
__global__ void k_bn_stats(const float* __restrict__ h, float* __restrict__ psum,
                           float* __restrict__ psq, int Nrows) {
    int f = threadIdx.x;
    float s = 0.f, q = 0.f;
    for (int r = blockIdx.x; r < Nrows; r += gridDim.x) {
        float v = h[(size_t)r * 256 + f];
        s += v;
        q += v * v;
    }
    psum[blockIdx.x * 256 + f] = s;
    psq[blockIdx.x * 256 + f] = q;
}

__global__ void k_bn_reduce(const float* __restrict__ psum, const float* __restrict__ psq,
                            const float* __restrict__ bnp, float* __restrict__ scale,
                            float* __restrict__ shift) {
    int f = threadIdx.x;
    double s = 0.0, q = 0.0;
    for (int b = 0; b < 256; b++) {
        s += (double)psum[b * 256 + f];
        q += (double)psq[b * 256 + f];
    }
    double mu = s / (double)NN;
    double var = q / (double)NN - mu * mu;
    float g, bt;
    if (f < 128) { g = bnp[f];             bt = bnp[128 + f]; }
    else         { g = bnp[256 + f - 128]; bt = bnp[384 + f - 128]; }
    float sc = g * rsqrtf((float)var + BN_EPS);
    scale[f] = sc;
    shift[f] = bt - (float)mu * sc;
}

// apply BN; WB: also emit bf16 hi/lo slice (stride Kstr) + fp16 copy. FP32W: keep fp32 write.
template <bool WB, bool FP32W>
__global__ void k_bn_apply(float4* __restrict__ h, const float* __restrict__ scale,
                           const float* __restrict__ shift,
                           __nv_bfloat16* __restrict__ xh, __nv_bfloat16* __restrict__ xl,
                           __half* __restrict__ xf, int Kstr) {
    int i = blockIdx.x * blockDim.x + threadIdx.x;  // NN*64 float4s
    if (i >= NN * 64) return;
    int c = (i & 63) * 4;
    float4 v = h[i];
    v.x = fmaf(v.x, scale[c + 0], shift[c + 0]);
    v.y = fmaf(v.y, scale[c + 1], shift[c + 1]);
    v.z = fmaf(v.z, scale[c + 2], shift[c + 2]);
    v.w = fmaf(v.w, scale[c + 3], shift[c + 3]);
    if (FP32W) h[i] = v;
    if (WB) {
        int r = i >> 6;
        union { __nv_bfloat16 b[4]; uint2 u; } H, L;
        split_bf16(v.x, H.b[0], L.b[0]);
        split_bf16(v.y, H.b[1], L.b[1]);
        split_bf16(v.z, H.b[2], L.b[2]);
        split_bf16(v.w, H.b[3], L.b[3]);
        size_t o = (size_t)r * Kstr + c;
        *(uint2*)&xh[o] = H.u;
        *(uint2*)&xl[o] = L.u;
        union { __half hh[4]; uint2 u; } F;
        F.hh[0] = __float2half_rn(v.x);
        F.hh[1] = __float2half_rn(v.y);
        F.hh[2] = __float2half_rn(v.z);
        F.hh[3] = __float2half_rn(v.w);
        *(uint2*)&xf[(size_t)r * 256 + c] = F.u;
    }
}

// ---------------- z = h2 @ We + be ----------------
__global__ void k_zproj(const float* __restrict__ h, const float* __restrict__ We,
                        const float* __restrict__ be, float* __restrict__ z) {
    __shared__ float Ws[256 * 16];
    for (int i = threadIdx.x; i < 4096; i += blockDim.x) Ws[i] = We[i];
    __syncthreads();
    int t = blockIdx.x * blockDim.x + threadIdx.x;
    int r = t >> 4, m = t & 15;
    float acc = __ldg(&be[m]);
    const float4* hp = (const float4*)(h + (size_t)r * 256);
#pragma unroll 4
    for (int k4 = 0; k4 < 64; k4++) {
        float4 hv = hp[k4];
        int k = k4 * 4;
        acc += hv.x * Ws[k * 16 + m] + hv.y * Ws[(k + 1) * 16 + m] +
               hv.z * Ws[(k + 2) * 16 + m] + hv.w * Ws[(k + 3) * 16 + m];
    }
    z[t] = acc;
}

// ---------------- per-edge score + softmax over 16 machines ----------------
__global__ void k_edge(const int* __restrict__ rows, const int* __restrict__ cols,
                       const float* __restrict__ vals, const float* __restrict__ z,
                       float* __restrict__ out) {
    int idx = blockIdx.x * blockDim.x + threadIdx.x;
    int e = idx >> 4, m = idx & 15;
    int r = __ldg(&rows[e]);
    int c = __ldg(&cols[e]);
    float s = __ldg(&vals[e]) * (__ldg(&z[r * 16 + m]) + __ldg(&z[c * 16 + m]));
    float mx = s;
#pragma unroll
    for (int off = 8; off > 0; off >>= 1)
        mx = fmaxf(mx, __shfl_xor_sync(0xffffffffu, mx, off, 16));
    float ex = __expf(s - mx);
    float sm = ex;
#pragma unroll
    for (int off = 8; off > 0; off >>= 1)
        sm += __shfl_xor_sync(0xffffffffu, sm, off, 16);
    out[idx] = ex / sm;
}

// ---------------- launch ----------------
extern "C" void kernel_launch(void* const* d_in, const int* in_sizes, int n_in,
                              void* d_out, int out_size) {
    const float* x    = (const float*)d_in[0];
    const int*   rows = (const int*)d_in[1];
    const int*   cols = (const int*)d_in[2];
    const float* vals = (const float*)d_in[3];
    const float* l0Wa = (const float*)d_in[4];
    const float* l0Wb = (const float*)d_in[5];
    const float* l0bn = (const float*)d_in[6];
    const float* l1Wa = (const float*)d_in[7];
    const float* l1Wb = (const float*)d_in[8];
    const float* l1bn = (const float*)d_in[9];
    const float* We   = (const float*)d_in[10];
    const float* be   = (const float*)d_in[11];
    float* out = (float*)d_out;

    float *h, *h2, *z, *evalp, *psum, *psq, *scale, *shift;
    int *rowptr, *cnt, *cursor, *ecol;
    __half *f16x, *f16a, *f16b, *f16c;
    __nv_bfloat16 *X0h, *X0l, *X1h, *X1l, *Bt0h, *Bt0l, *Bt1h, *Bt1l;
    cudaGetSymbolAddress((void**)&h, g_h);
    cudaGetSymbolAddress((void**)&h2, g_h2);
    cudaGetSymbolAddress((void**)&z, g_z);
    cudaGetSymbolAddress((void**)&evalp, g_eval);
    cudaGetSymbolAddress((void**)&psum, g_psum);
    cudaGetSymbolAddress((void**)&psq, g_psq);
    cudaGetSymbolAddress((void**)&scale, g_scale);
    cudaGetSymbolAddress((void**)&shift, g_shift);
    cudaGetSymbolAddress((void**)&rowptr, g_rowptr);
    cudaGetSymbolAddress((void**)&cnt, g_cnt);
    cudaGetSymbolAddress((void**)&cursor, g_cursor);
    cudaGetSymbolAddress((void**)&ecol, g_ecol);
    cudaGetSymbolAddress((void**)&f16x, g_f16x);
    cudaGetSymbolAddress((void**)&f16a, g_f16a);
    cudaGetSymbolAddress((void**)&f16b, g_f16b);
    cudaGetSymbolAddress((void**)&f16c, g_f16c);
    cudaGetSymbolAddress((void**)&X0h, g_X0h);
    cudaGetSymbolAddress((void**)&X0l, g_X0l);
    cudaGetSymbolAddress((void**)&X1h, g_X1h);
    cudaGetSymbolAddress((void**)&X1l, g_X1l);
    cudaGetSymbolAddress((void**)&Bt0h, g_Bt0h);
    cudaGetSymbolAddress((void**)&Bt0l, g_Bt0l);
    cudaGetSymbolAddress((void**)&Bt1h, g_Bt1h);
    cudaGetSymbolAddress((void**)&Bt1l, g_Bt1l);

    cudaFuncSetAttribute(k_gemm_mma, cudaFuncAttributeMaxDynamicSharedMemorySize, GSM);

    // ---- CSR build ----
    k_zero_int<<<(NN + 255) / 256, 256>>>(cnt, NN);
    k_hist<<<(EE + 255) / 256, 256>>>(rows, cnt);
    k_scan<<<1, 1024>>>(cnt, rowptr);
    k_copy_int<<<(NN + 255) / 256, 256>>>(rowptr, cursor, NN);
    k_scatter<<<(EE + 255) / 256, 256>>>(rows, cols, vals, cursor, ecol, evalp);

    // ---- combined transposed weights (bf16 hi/lo) ----
    k_prep_bt<<<(256 * 512 + 255) / 256, 256>>>(l0Wa, l0Wb, Bt0h, Bt0l, 128);
    k_prep_bt<<<(256 * 1024 + 255) / 256, 256>>>(l1Wa, l1Wb, Bt1h, Bt1l, 256);

    dim3 ggrid((NN + 127) / 128, 2);

    // ---- layer 0 (D=128, CQ=16; K=512; slices at cols 0,128,256,384) ----
    k_split_x<<<(NN * 32 + 255) / 256, 256>>>((const float4*)x, X0h, X0l, f16x, 32, 512, NN * 32);
    k_spmm_h<16, 8, 1><<<(NN + 7) / 8, 128>>>((const uint4*)f16x, (uint4*)f16a, rowptr, ecol, evalp, X0h + 128, X0l + 128, 512);
    k_spmm_h<16, 8, 1><<<(NN + 7) / 8, 128>>>((const uint4*)f16a, (uint4*)f16b, rowptr, ecol, evalp, X0h + 256, X0l + 256, 512);
    k_spmm_h<16, 8, 0><<<(NN + 7) / 8, 128>>>((const uint4*)f16b, (uint4*)f16c, rowptr, ecol, evalp, nullptr, nullptr, 0);
    k_spmm_h<16, 8, 2><<<(NN + 7) / 8, 128>>>((const uint4*)f16c, nullptr, rowptr, ecol, evalp, X0h + 384, X0l + 384, 512);
    k_gemm_mma<<<ggrid, 256, GSM>>>(X0h, X0l, Bt0h, Bt0l, h, 512, NN);
    k_bn_stats<<<256, 256>>>(h, psum, psq, NN);
    k_bn_reduce<<<1, 256>>>(psum, psq, l0bn, scale, shift);
    k_bn_apply<true, false><<<(NN * 64 + 255) / 256, 256>>>((float4*)h, scale, shift, X1h, X1l, f16x, 1024);

    // ---- layer 1 (D=256, CQ=32; K=1024; slices at cols 0,256,512,768) ----
    k_spmm_h<32, 4, 1><<<(NN + 3) / 4, 128>>>((const uint4*)f16x, (uint4*)f16a, rowptr, ecol, evalp, X1h + 256, X1l + 256, 1024);
    k_spmm_h<32, 4, 1><<<(NN + 3) / 4, 128>>>((const uint4*)f16a, (uint4*)f16b, rowptr, ecol, evalp, X1h + 512, X1l + 512, 1024);
    k_spmm_h<32, 4, 0><<<(NN + 3) / 4, 128>>>((const uint4*)f16b, (uint4*)f16c, rowptr, ecol, evalp, nullptr, nullptr, 0);
    k_spmm_h<32, 4, 2><<<(NN + 3) / 4, 128>>>((const uint4*)f16c, nullptr, rowptr, ecol, evalp, X1h + 768, X1l + 768, 1024);
    k_gemm_mma<<<ggrid, 256, GSM>>>(X1h, X1l, Bt1h, Bt1l, h2, 1024, NN);
    k_bn_stats<<<256, 256>>>(h2, psum, psq, NN);
    k_bn_reduce<<<1, 256>>>(psum, psq, l1bn, scale, shift);
    k_bn_apply<false, true><<<(NN * 64 + 255) / 256, 256>>>((float4*)h2, scale, shift, nullptr, nullptr, nullptr, 0);

    // ---- final projection + per-edge softmax ----
    k_zproj<<<(NN * 16) / 256, 256>>>(h2, We, be, z);
    k_edge<<<(EE * 16) / 256, 256>>>(rows, cols, vals, z, out);
}